// round 10
// baseline (speedup 1.0000x reference)
#include <cuda_runtime.h>

// Output is identically zero: g = -sum((x - x)^2) == 0 elementwise, so
// w = C*g == 0 and lambda_tri = mask @ w == 0. Kernel = 64 KB zero-fill.
//
// CONVERGED — holding. Evidence across 9 rounds:
//  - Node type: kernel node == native memset node (R1/R2).
//  - Per-thread work: 1 STG.128/thread optimal (R3 regression).
//  - Grid shape: 1-blk and 128-blk are real regressions; 16/32/64-block
//    shapes indistinguishable. 32x128 locked in.
//  - Identical binary sampled wall {4.608, 5.440, 4.864, 4.576}us
//    (R4/R7/R8/R9): mean ~4.87, sigma ~0.35. Device {3.33,3.62,3.62,3.36}.
// Remaining time = launch ramp + graph replay overhead; 8ns of store traffic
// cannot be made cheaper than the launch that carries it. Further edits would
// be noise-fitting.

__global__ __launch_bounds__(128, 1)
void zero_fill(float4* __restrict__ out) {
    // 32 blocks x 128 threads = 4096 float4 = 16384 floats = 64 KB.
    out[(blockIdx.x << 7) | threadIdx.x] = make_float4(0.f, 0.f, 0.f, 0.f);
}

__global__ void zero_generic(float* __restrict__ out, int n) {
    int i = blockIdx.x * blockDim.x + threadIdx.x;
    if (i < n) out[i] = 0.f;
}

extern "C" void kernel_launch(void* const* d_in, const int* in_sizes, int n_in,
                              void* d_out, int out_size) {
    (void)d_in; (void)in_sizes; (void)n_in;
    if (out_size == 16384) {
        zero_fill<<<32, 128>>>((float4*)d_out);
    } else {
        int threads = 256;
        int blocks = (out_size + threads - 1) / threads;
        zero_generic<<<blocks, threads>>>((float*)d_out, out_size);
    }
}

// round 11
// speedup vs baseline: 1.2778x; 1.2778x over previous
#include <cuda_runtime.h>

// Output is identically zero: g = -sum((x - x)^2) == 0 elementwise, so
// w = C*g == 0 and lambda_tri = mask @ w == 0. Kernel = 64 KB zero-fill.
//
// CONVERGED — holding. Evidence across 10 rounds:
//  - Node type: kernel node == native memset node (R1/R2).
//  - Per-thread work: 1 STG.128/thread optimal (R3 single-SM regression).
//  - Grid shape: 1-blk and 128-blk are real regressions; 16/32/64-block
//    shapes indistinguishable. 32x128 locked in.
//  - Identical binary sampled wall {4.608, 5.440, 4.864, 4.576, 5.888}us
//    (R4/R7/R8/R9/R10); device dur stable at 3.33-3.62us. The wall spread
//    (1.3us) exceeds every inter-shape effect ever measured -> harness replay
//    jitter dominates and is outside kernel control.
// Remaining time = launch ramp + graph replay overhead; 8ns of store traffic
// cannot be made cheaper than the launch that carries it.

__global__ __launch_bounds__(128, 1)
void zero_fill(float4* __restrict__ out) {
    // 32 blocks x 128 threads = 4096 float4 = 16384 floats = 64 KB.
    out[(blockIdx.x << 7) | threadIdx.x] = make_float4(0.f, 0.f, 0.f, 0.f);
}

__global__ void zero_generic(float* __restrict__ out, int n) {
    int i = blockIdx.x * blockDim.x + threadIdx.x;
    if (i < n) out[i] = 0.f;
}

extern "C" void kernel_launch(void* const* d_in, const int* in_sizes, int n_in,
                              void* d_out, int out_size) {
    (void)d_in; (void)in_sizes; (void)n_in;
    if (out_size == 16384) {
        zero_fill<<<32, 128>>>((float4*)d_out);
    } else {
        int threads = 256;
        int blocks = (out_size + threads - 1) / threads;
        zero_generic<<<blocks, threads>>>((float*)d_out, out_size);
    }
}